// round 4
// baseline (speedup 1.0000x reference)
#include <cuda_runtime.h>

namespace {
constexpr int K     = 9;
constexpr int NB    = 64;
constexpr int NH    = 32;
constexpr int NW    = 32;
constexpr int NCELL = NH * NW;       // 1024
constexpr int NT    = 50;
constexpr int NLAB  = 2 * K + 3;     // 21
constexpr int CH    = 2 * K + 2;     // 20
constexpr float THR = 80.0f;
constexpr float IMW = 640.0f;
constexpr float IMH = 480.0f;
constexpr float SIL = 0.6f;
constexpr float OBJ = 5.0f;
constexpr int   NBLK = 256;          // 4 cell-chunks x 64 batches
constexpr float CELLW = IMW / NW;    // 20 px
constexpr float CELLH = IMH / NH;    // 15 px
}

__device__ float        g_partials[NBLK];
__device__ unsigned int g_count = 0;

__global__ __launch_bounds__(256) void region_loss_kernel(
    const float* __restrict__ out,
    const float* __restrict__ tgt,
    const int*   __restrict__ epoch_p,
    float*       __restrict__ loss)
{
    __shared__ float2 sXY[NT][K];                  // gt corners, pixel space
    __shared__ float sbx0[NT], sbx1[NT], sby0[NT], sby1[NT];
    __shared__ int   scell[NT];
    __shared__ unsigned s_inv[2];
    __shared__ float swarp[8];
    __shared__ int   s_last;

    const int bid  = blockIdx.x;
    const int b    = bid >> 2;
    const int tid  = threadIdx.x;
    const int cell = ((bid & 3) << 8) | tid;       // 0..1023

    // ---- 1) prediction + epoch loads first: DRAM latency overlaps staging
    const int epoch = epoch_p ? __ldg(epoch_p) : 20;
    const float* ob = out + (size_t)(b * CH) * NCELL + cell;
    float raw[2 * K + 1];
    #pragma unroll
    for (int c = 0; c < 2 * K + 1; c++) raw[c] = ob[c * NCELL];

    // ---- 2) stage targets (coalesced scalar loads -> float2 smem), pixel space
    const float* tb = tgt + (size_t)b * (NT * NLAB);
    for (int idx = tid; idx < NT * 2 * K; idx += 256) {
        int t = idx / (2 * K), c = idx - t * (2 * K);
        float v = tb[t * NLAB + 1 + c];
        float* dst = (float*)&sXY[t][c >> 1];
        dst[c & 1] = v * ((c & 1) ? IMH : IMW);
    }
    if (tid < 64) {   // validity prefix via ballot (x0 != 0)
        bool v = (tid < NT) && (tb[tid * NLAB + 1] != 0.0f);
        unsigned m = __ballot_sync(0xffffffffu, v);
        if ((tid & 31) == 0) s_inv[tid >> 5] = ~m;
    }
    __syncthreads();

    // ---- 3) per-target bbox + cell index
    if (tid < NT) {
        float2 c0 = sXY[tid][0];
        float mnx = c0.x, mxx = c0.x, mny = c0.y, mxy = c0.y;
        #pragma unroll
        for (int k = 1; k < K; k++) {
            float2 c = sXY[tid][k];
            mnx = fminf(mnx, c.x); mxx = fmaxf(mxx, c.x);
            mny = fminf(mny, c.y); mxy = fmaxf(mxy, c.y);
        }
        sbx0[tid] = mnx; sbx1[tid] = mxx; sby0[tid] = mny; sby1[tid] = mxy;
        int gi0 = (int)floorf(c0.x * (1.0f / CELLW));
        int gj0 = (int)floorf(c0.y * (1.0f / CELLH));
        scell[tid] = (gi0 >= 0 && gi0 < NW && gj0 >= 0 && gj0 < NH)
                         ? gj0 * NW + gi0 : -1;
    }
    __syncthreads();

    const unsigned inv0 = s_inv[0], inv1 = s_inv[1];
    const int nv = inv0 ? (__ffs(inv0) - 1) : (inv1 ? 31 + __ffs(inv1) : 64);
    const bool do_conf = epoch > 15;
    const float i_f = (float)(cell & (NW - 1));
    const float j_f = (float)(cell >> 5);

    // ---- 4) predictions in pixel space
    raw[0]      = 1.0f / (1.0f + __expf(-raw[0]));
    raw[1]      = 1.0f / (1.0f + __expf(-raw[1]));
    float confp = 1.0f / (1.0f + __expf(-raw[2 * K]));

    float px[K], py[K];
    float pminx = 1e30f, pmaxx = -1e30f, pminy = 1e30f, pmaxy = -1e30f;
    #pragma unroll
    for (int k = 0; k < K; k++) {
        px[k] = (raw[2 * k]     + i_f) * CELLW;
        py[k] = (raw[2 * k + 1] + j_f) * CELLH;
        pminx = fminf(pminx, px[k]); pmaxx = fmaxf(pmaxx, px[k]);
        pminy = fminf(pminy, py[k]); pmaxy = fmaxf(pmaxy, py[k]);
    }

    const float inv_denK = (1.0f / (float)K) / (__expf(2.0f) - 1.0f + 1e-5f);

    // ---- 5) hit detection (cheap scan)
    int thit = -1;
    for (int t = 0; t < nv; t++)
        if (scell[t] == cell) thit = t;

    float lcl = 0.0f;
    if (thit >= 0) {
        // target cell: coord loss + OBJ-weighted conf loss (silent test irrelevant)
        float2 g0 = sXY[thit][0];
        float gx0 = floorf(g0.x * (1.0f / CELLW));
        float gy0 = floorf(g0.y * (1.0f / CELLH));
        float acc = 0.0f;
        #pragma unroll
        for (int k = 0; k < K; k++) {
            float2 g = sXY[thit][k];
            float ex = raw[2 * k]     - (g.x * (1.0f / CELLW) - gx0);
            float ey = raw[2 * k + 1] - (g.y * (1.0f / CELLH) - gy0);
            lcl += 0.5f * (ex * ex + ey * ey);
            float dx = g.x - px[k], dy = g.y - py[k];
            float d2 = fmaf(dx, dx, dy * dy);
            if (d2 < THR * THR)
                acc += __expf(2.0f - sqrtf(d2) * (2.0f / THR)) - 1.0f;
        }
        if (do_conf) {
            float e = confp - acc * inv_denK;
            lcl += 0.5f * OBJ * e * e;
        }
    } else if (do_conf) {
        // silent-zone boolean: any target with mean corner-conf > SIL?
        // Exact prune: mean > 0.6 requires >= 6 of 9 corners within THR.
        bool silent = false;
        for (int t = 0; t < nv && !silent; t++) {
            float sepx = fmaxf(sbx0[t] - pmaxx, pminx - sbx1[t]);
            float sepy = fmaxf(sby0[t] - pmaxy, pminy - sby1[t]);
            if (sepx >= THR || sepy >= THR) continue;   // all corners >= THR
            int cnt = 0;
            #pragma unroll
            for (int k = 0; k < K; k++) {
                float2 g = sXY[t][k];
                float dx = g.x - px[k], dy = g.y - py[k];
                float d2 = fmaf(dx, dx, dy * dy);
                cnt += (d2 < THR * THR);
            }
            if (cnt >= 6) {       // rare: compute the exact conf sum
                float acc = 0.0f;
                #pragma unroll
                for (int k = 0; k < K; k++) {
                    float2 g = sXY[t][k];
                    float dx = g.x - px[k], dy = g.y - py[k];
                    float d2 = fmaf(dx, dx, dy * dy);
                    if (d2 < THR * THR)
                        acc += __expf(2.0f - sqrtf(d2) * (2.0f / THR)) - 1.0f;
                }
                if (acc * inv_denK > SIL) silent = true;
            }
        }
        if (!silent) lcl = 0.5f * confp * confp;   // NOOBJ, tconf = 0
    }

    // ---- 6) block reduce -> partial; last block reduces 256 partials
    #pragma unroll
    for (int o = 16; o > 0; o >>= 1)
        lcl += __shfl_xor_sync(0xffffffffu, lcl, o);
    if ((tid & 31) == 0) swarp[tid >> 5] = lcl;
    __syncthreads();
    if (tid < 8) {
        float v = swarp[tid];
        #pragma unroll
        for (int o = 4; o > 0; o >>= 1)
            v += __shfl_xor_sync(0xffu, v, o);
        if (tid == 0) {
            g_partials[bid] = v;
            __threadfence();
            unsigned old = atomicAdd(&g_count, 1);
            s_last = (old == NBLK - 1) ? 1 : 0;
        }
    }
    __syncthreads();
    if (s_last) {
        float v = g_partials[tid];
        #pragma unroll
        for (int o = 16; o > 0; o >>= 1)
            v += __shfl_xor_sync(0xffffffffu, v, o);
        if ((tid & 31) == 0) swarp[tid >> 5] = v;
        __syncthreads();
        if (tid < 8) {
            float w = swarp[tid];
            #pragma unroll
            for (int o = 4; o > 0; o >>= 1)
                w += __shfl_xor_sync(0xffu, w, o);
            if (tid == 0) {
                loss[0] = w;
                g_count = 0;   // reset for next graph replay
            }
        }
    }
}

extern "C" void kernel_launch(void* const* d_in, const int* in_sizes, int n_in,
                              void* d_out, int out_size)
{
    const float* output = (const float*)d_in[0];
    const float* target = (const float*)d_in[1];
    const int*   epoch  = (n_in > 2) ? (const int*)d_in[2] : nullptr;
    float* loss = (float*)d_out;

    region_loss_kernel<<<NBLK, 256>>>(output, target, epoch, loss);
    (void)in_sizes; (void)out_size;
}

// round 5
// speedup vs baseline: 1.0389x; 1.0389x over previous
#include <cuda_runtime.h>

namespace {
constexpr int K     = 9;
constexpr int NB    = 64;
constexpr int NH    = 32;
constexpr int NW    = 32;
constexpr int NCELL = NH * NW;       // 1024
constexpr int NT    = 50;
constexpr int NLAB  = 2 * K + 3;     // 21
constexpr int CH    = 2 * K + 2;     // 20
constexpr float THR = 80.0f;
constexpr float IMW = 640.0f;
constexpr float IMH = 480.0f;
constexpr float SIL = 0.6f;
constexpr float OBJ = 5.0f;
constexpr int   TPB  = 512;          // threads per block (half a batch)
constexpr int   NBLK = NB * NCELL / TPB;   // 128 blocks -> 1 CTA/SM, single wave
constexpr float CELLW = IMW / NW;    // 20 px
constexpr float CELLH = IMH / NH;    // 15 px
}

__device__ float        g_partials[NBLK];
__device__ unsigned int g_count = 0;

__global__ __launch_bounds__(TPB) void region_loss_kernel(
    const float* __restrict__ out,
    const float* __restrict__ tgt,
    const int*   __restrict__ epoch_p,
    float*       __restrict__ loss)
{
    __shared__ float2 sXY[NT][K];                  // gt corners, pixel space
    __shared__ float sbx0[NT], sbx1[NT], sby0[NT], sby1[NT];
    __shared__ int   scell[NT];
    __shared__ unsigned s_inv[2];
    __shared__ float swarp[TPB / 32];
    __shared__ int   s_last;

    const int bid  = blockIdx.x;
    const int b    = bid >> 1;                     // batch
    const int tid  = threadIdx.x;
    const int cell = ((bid & 1) << 9) | tid;       // 0..1023

    // ---- 1) prediction + epoch loads first: DRAM latency overlaps staging
    const int epoch = epoch_p ? __ldg(epoch_p) : 20;
    const float* ob = out + (size_t)(b * CH) * NCELL + cell;
    float raw[2 * K + 1];
    #pragma unroll
    for (int c = 0; c < 2 * K + 1; c++) raw[c] = ob[c * NCELL];

    // ---- 2) stage targets (coalesced), pixel space
    const float* tb = tgt + (size_t)b * (NT * NLAB);
    for (int idx = tid; idx < NT * 2 * K; idx += TPB) {
        int t = idx / (2 * K), c = idx - t * (2 * K);
        float v = tb[t * NLAB + 1 + c];
        float* dst = (float*)&sXY[t][c >> 1];
        dst[c & 1] = v * ((c & 1) ? IMH : IMW);
    }
    if (tid < 64) {   // validity prefix via ballot (x0 != 0)
        bool v = (tid < NT) && (tb[tid * NLAB + 1] != 0.0f);
        unsigned m = __ballot_sync(0xffffffffu, v);
        if ((tid & 31) == 0) s_inv[tid >> 5] = ~m;
    }
    __syncthreads();

    // ---- 3) per-target bbox + cell index
    if (tid < NT) {
        float2 c0 = sXY[tid][0];
        float mnx = c0.x, mxx = c0.x, mny = c0.y, mxy = c0.y;
        #pragma unroll
        for (int k = 1; k < K; k++) {
            float2 c = sXY[tid][k];
            mnx = fminf(mnx, c.x); mxx = fmaxf(mxx, c.x);
            mny = fminf(mny, c.y); mxy = fmaxf(mxy, c.y);
        }
        sbx0[tid] = mnx; sbx1[tid] = mxx; sby0[tid] = mny; sby1[tid] = mxy;
        int gi0 = (int)floorf(c0.x * (1.0f / CELLW));
        int gj0 = (int)floorf(c0.y * (1.0f / CELLH));
        scell[tid] = (gi0 >= 0 && gi0 < NW && gj0 >= 0 && gj0 < NH)
                         ? gj0 * NW + gi0 : -1;
    }
    __syncthreads();

    const unsigned inv0 = s_inv[0], inv1 = s_inv[1];
    const int nv = inv0 ? (__ffs(inv0) - 1) : (inv1 ? 31 + __ffs(inv1) : 64);
    const bool do_conf = epoch > 15;
    const float i_f = (float)(cell & (NW - 1));
    const float j_f = (float)(cell >> 5);

    // ---- 4) predictions in pixel space
    raw[0]      = 1.0f / (1.0f + __expf(-raw[0]));
    raw[1]      = 1.0f / (1.0f + __expf(-raw[1]));
    float confp = 1.0f / (1.0f + __expf(-raw[2 * K]));

    float px[K], py[K];
    float pminx = 1e30f, pmaxx = -1e30f, pminy = 1e30f, pmaxy = -1e30f;
    #pragma unroll
    for (int k = 0; k < K; k++) {
        px[k] = (raw[2 * k]     + i_f) * CELLW;
        py[k] = (raw[2 * k + 1] + j_f) * CELLH;
        pminx = fminf(pminx, px[k]); pmaxx = fmaxf(pmaxx, px[k]);
        pminy = fminf(pminy, py[k]); pmaxy = fmaxf(pmaxy, py[k]);
    }

    const float inv_denK = (1.0f / (float)K) / (__expf(2.0f) - 1.0f + 1e-5f);

    // ---- 5) hit detection
    int thit = -1;
    for (int t = 0; t < nv; t++)
        if (scell[t] == cell) thit = t;

    float lcl = 0.0f;
    if (thit >= 0) {
        // target cell: coord loss + OBJ-weighted conf loss
        float2 g0 = sXY[thit][0];
        float gx0 = floorf(g0.x * (1.0f / CELLW));
        float gy0 = floorf(g0.y * (1.0f / CELLH));
        float acc = 0.0f;
        #pragma unroll
        for (int k = 0; k < K; k++) {
            float2 g = sXY[thit][k];
            float ex = raw[2 * k]     - (g.x * (1.0f / CELLW) - gx0);
            float ey = raw[2 * k + 1] - (g.y * (1.0f / CELLH) - gy0);
            lcl += 0.5f * (ex * ex + ey * ey);
            float dx = g.x - px[k], dy = g.y - py[k];
            float d2 = fmaf(dx, dx, dy * dy);
            if (d2 < THR * THR)
                acc += __expf(2.0f - sqrtf(d2) * (2.0f / THR)) - 1.0f;
        }
        if (do_conf) {
            float e = confp - acc * inv_denK;
            lcl += 0.5f * OBJ * e * e;
        }
    } else if (do_conf) {
        // silent-zone boolean: mean > 0.6 requires >= 6 of 9 corners within THR
        bool silent = false;
        for (int t = 0; t < nv && !silent; t++) {
            float sepx = fmaxf(sbx0[t] - pmaxx, pminx - sbx1[t]);
            float sepy = fmaxf(sby0[t] - pmaxy, pminy - sby1[t]);
            if (sepx >= THR || sepy >= THR) continue;
            int cnt = 0;
            #pragma unroll
            for (int k = 0; k < K; k++) {
                float2 g = sXY[t][k];
                float dx = g.x - px[k], dy = g.y - py[k];
                float d2 = fmaf(dx, dx, dy * dy);
                cnt += (d2 < THR * THR);
            }
            if (cnt >= 6) {
                float acc = 0.0f;
                #pragma unroll
                for (int k = 0; k < K; k++) {
                    float2 g = sXY[t][k];
                    float dx = g.x - px[k], dy = g.y - py[k];
                    float d2 = fmaf(dx, dx, dy * dy);
                    if (d2 < THR * THR)
                        acc += __expf(2.0f - sqrtf(d2) * (2.0f / THR)) - 1.0f;
                }
                if (acc * inv_denK > SIL) silent = true;
            }
        }
        if (!silent) lcl = 0.5f * confp * confp;   // NOOBJ, tconf = 0
    }

    // ---- 6) block reduce -> partial; last block reduces NBLK partials
    #pragma unroll
    for (int o = 16; o > 0; o >>= 1)
        lcl += __shfl_xor_sync(0xffffffffu, lcl, o);
    if ((tid & 31) == 0) swarp[tid >> 5] = lcl;
    __syncthreads();
    if (tid < TPB / 32) {              // 16 lanes
        float v = swarp[tid];
        #pragma unroll
        for (int o = 8; o > 0; o >>= 1)
            v += __shfl_xor_sync(0xffffu, v, o);
        if (tid == 0) {
            g_partials[bid] = v;
            __threadfence();
            unsigned old = atomicAdd(&g_count, 1);
            s_last = (old == NBLK - 1) ? 1 : 0;
        }
    }
    __syncthreads();
    if (s_last && tid < NBLK) {        // 128 lanes
        float v = g_partials[tid];
        #pragma unroll
        for (int o = 16; o > 0; o >>= 1)
            v += __shfl_xor_sync(0xffffffffu, v, o);
        if ((tid & 31) == 0) swarp[tid >> 5] = v;
        __syncwarp(0xffffffffu);
        // cross-warp combine: 4 partial warps -> lane adds from smem
        if (tid == 0) {
            // ensure other warps' swarp stores are visible
        }
    }
    if (s_last) {
        __syncthreads();
        if (tid == 0) {
            float w = swarp[0] + swarp[1] + swarp[2] + swarp[3];
            loss[0] = w;
            g_count = 0;   // reset for next graph replay
        }
    }
}

extern "C" void kernel_launch(void* const* d_in, const int* in_sizes, int n_in,
                              void* d_out, int out_size)
{
    const float* output = (const float*)d_in[0];
    const float* target = (const float*)d_in[1];
    const int*   epoch  = (n_in > 2) ? (const int*)d_in[2] : nullptr;
    float* loss = (float*)d_out;

    region_loss_kernel<<<NBLK, TPB>>>(output, target, epoch, loss);
    (void)in_sizes; (void)out_size;
}